// round 1
// baseline (speedup 1.0000x reference)
#include <cuda_runtime.h>
#include <math.h>

#define Bv    128
#define Dv    128
#define NMEM  200000
#define K1v   2048
#define INV_T (1.0f / 0.07f)

// ---------------------------------------------------------------------------
// Kernel 1: gather 4 memory rows per (b,k), compute 6 dot products / T.
// One warp per (b,k). blockDim = 256 (8 warps) -> grid (K1/8, B).
// outs layout: [6, B, K1] with stack order
//   0: w_ori . l      (out_l_ori)
//   1: w_l   . ab     (out_ab_l)
//   2: w_ab  . ori    (out_ori_ab)
//   3: w_comp. ab     (out_ab_comp)
//   4: w_comp. l      (out_l_comp)
//   5: w_ori . comp   (out_comp_ori)
// ---------------------------------------------------------------------------
__global__ __launch_bounds__(256) void gather_dots_kernel(
    const float* __restrict__ l,
    const float* __restrict__ ab,
    const float* __restrict__ ori,
    const float* __restrict__ comp,
    const int*   __restrict__ idx,
    const float* __restrict__ mem_l,
    const float* __restrict__ mem_ab,
    const float* __restrict__ mem_ori,
    const float* __restrict__ mem_comp,
    float* __restrict__ outs)
{
    __shared__ float4 s_l[32], s_ab[32], s_ori[32], s_comp[32];
    __shared__ int    s_idx[8];

    const int b   = blockIdx.y;
    const int tid = threadIdx.x;

    if (tid < 32) {
        s_l [tid] = reinterpret_cast<const float4*>(l  + b * Dv)[tid];
        s_ab[tid] = reinterpret_cast<const float4*>(ab + b * Dv)[tid];
    } else if (tid < 64) {
        const int t = tid - 32;
        s_ori [t] = reinterpret_cast<const float4*>(ori  + b * Dv)[t];
        s_comp[t] = reinterpret_cast<const float4*>(comp + b * Dv)[t];
    } else if (tid < 72) {
        const int t = tid - 64;
        s_idx[t] = idx[b * K1v + blockIdx.x * 8 + t];
    }
    __syncthreads();

    const int warp = tid >> 5;
    const int lane = tid & 31;
    const int k    = blockIdx.x * 8 + warp;
    const long long row = s_idx[warp];

    const float4 wl  = reinterpret_cast<const float4*>(mem_l    + row * Dv)[lane];
    const float4 wab = reinterpret_cast<const float4*>(mem_ab   + row * Dv)[lane];
    const float4 wor = reinterpret_cast<const float4*>(mem_ori  + row * Dv)[lane];
    const float4 wco = reinterpret_cast<const float4*>(mem_comp + row * Dv)[lane];

    const float4 vl  = s_l[lane];
    const float4 vab = s_ab[lane];
    const float4 vor = s_ori[lane];
    const float4 vco = s_comp[lane];

    float s0 = wor.x * vl.x  + wor.y * vl.y  + wor.z * vl.z  + wor.w * vl.w;   // l_ori
    float s1 = wl.x  * vab.x + wl.y  * vab.y + wl.z  * vab.z + wl.w  * vab.w;  // ab_l
    float s2 = wab.x * vor.x + wab.y * vor.y + wab.z * vor.z + wab.w * vor.w;  // ori_ab
    float s3 = wco.x * vab.x + wco.y * vab.y + wco.z * vab.z + wco.w * vab.w;  // ab_comp
    float s4 = wco.x * vl.x  + wco.y * vl.y  + wco.z * vl.z  + wco.w * vl.w;   // l_comp
    float s5 = wor.x * vco.x + wor.y * vco.y + wor.z * vco.z + wor.w * vco.w;  // comp_ori

    #pragma unroll
    for (int off = 16; off > 0; off >>= 1) {
        s0 += __shfl_xor_sync(0xFFFFFFFFu, s0, off);
        s1 += __shfl_xor_sync(0xFFFFFFFFu, s1, off);
        s2 += __shfl_xor_sync(0xFFFFFFFFu, s2, off);
        s3 += __shfl_xor_sync(0xFFFFFFFFu, s3, off);
        s4 += __shfl_xor_sync(0xFFFFFFFFu, s4, off);
        s5 += __shfl_xor_sync(0xFFFFFFFFu, s5, off);
    }

    if (lane == 0) {
        const long long base   = (long long)b * K1v + k;
        const long long stride = (long long)Bv * K1v;
        outs[0 * stride + base] = s0 * INV_T;
        outs[1 * stride + base] = s1 * INV_T;
        outs[2 * stride + base] = s2 * INV_T;
        outs[3 * stride + base] = s3 * INV_T;
        outs[4 * stride + base] = s4 * INV_T;
        outs[5 * stride + base] = s5 * INV_T;
    }
}

// ---------------------------------------------------------------------------
// Kernel 2: EMA update of the 128 selected rows in the OUTPUT copies.
// Single block of 128 threads; serial over b so that duplicate y values
// resolve as "last index wins" (matching jnp .at[y].set semantics).
// Reads ORIGINAL memory banks (inputs are never modified).
// ---------------------------------------------------------------------------
__global__ void ema_update_kernel(
    const float* __restrict__ l,
    const float* __restrict__ ab,
    const float* __restrict__ ori,
    const float* __restrict__ comp,
    const int*   __restrict__ y,
    const float* __restrict__ mem_l,
    const float* __restrict__ mem_ab,
    const float* __restrict__ mem_ori,
    const float* __restrict__ mem_comp,
    float* __restrict__ out_l,
    float* __restrict__ out_ab,
    float* __restrict__ out_ori,
    float* __restrict__ out_comp)
{
    const int t = threadIdx.x;  // 0..127
    __shared__ float red[4];

    const float* vs[4] = {l, ab, ori, comp};
    const float* ms[4] = {mem_l, mem_ab, mem_ori, mem_comp};
    float*       os[4] = {out_l, out_ab, out_ori, out_comp};

    for (int b = 0; b < Bv; ++b) {
        const long long row = y[b];
        #pragma unroll
        for (int m = 0; m < 4; ++m) {
            float p  = ms[m][row * Dv + t] * 0.5f + vs[m][b * Dv + t] * 0.5f;
            float sq = p * p;
            #pragma unroll
            for (int off = 16; off > 0; off >>= 1)
                sq += __shfl_xor_sync(0xFFFFFFFFu, sq, off);
            if ((t & 31) == 0) red[t >> 5] = sq;
            __syncthreads();
            const float norm = sqrtf(red[0] + red[1] + red[2] + red[3]);
            os[m][row * Dv + t] = p / norm;
            __syncthreads();
        }
    }
}

// ---------------------------------------------------------------------------
extern "C" void kernel_launch(void* const* d_in, const int* in_sizes, int n_in,
                              void* d_out, int out_size)
{
    const float* l        = (const float*)d_in[0];
    const float* ab       = (const float*)d_in[1];
    const float* ori      = (const float*)d_in[2];
    const float* comp     = (const float*)d_in[3];
    const int*   y        = (const int*)  d_in[4];
    const int*   idx      = (const int*)  d_in[5];
    const float* mem_l    = (const float*)d_in[6];
    const float* mem_ab   = (const float*)d_in[7];
    const float* mem_ori  = (const float*)d_in[8];
    const float* mem_comp = (const float*)d_in[9];

    float* out = (float*)d_out;

    const long long OUTS_ELEMS = 6LL * Bv * K1v;          // 1,572,864
    const long long MEM_ELEMS  = (long long)NMEM * Dv;     // 25,600,000

    float* out_outs = out;
    float* out_ml   = out + OUTS_ELEMS;
    float* out_mab  = out_ml  + MEM_ELEMS;
    float* out_mori = out_mab + MEM_ELEMS;
    float* out_mco  = out_mori + MEM_ELEMS;

    // 1) gather + dots
    dim3 grid(K1v / 8, Bv);
    gather_dots_kernel<<<grid, 256>>>(l, ab, ori, comp, idx,
                                      mem_l, mem_ab, mem_ori, mem_comp,
                                      out_outs);

    // 2) copy memory banks into the output (updated rows overwritten next)
    const size_t memBytes = (size_t)MEM_ELEMS * sizeof(float);
    cudaMemcpyAsync(out_ml,   mem_l,    memBytes, cudaMemcpyDeviceToDevice, 0);
    cudaMemcpyAsync(out_mab,  mem_ab,   memBytes, cudaMemcpyDeviceToDevice, 0);
    cudaMemcpyAsync(out_mori, mem_ori,  memBytes, cudaMemcpyDeviceToDevice, 0);
    cudaMemcpyAsync(out_mco,  mem_comp, memBytes, cudaMemcpyDeviceToDevice, 0);

    // 3) EMA-update the 128 selected rows (reads original banks)
    ema_update_kernel<<<1, 128>>>(l, ab, ori, comp, y,
                                  mem_l, mem_ab, mem_ori, mem_comp,
                                  out_ml, out_mab, out_mori, out_mco);
}

// round 2
// speedup vs baseline: 2.7939x; 2.7939x over previous
#include <cuda_runtime.h>
#include <math.h>

#define Bv    128
#define Dv    128
#define NMEM  200000
#define K1v   2048
#define INV_T (1.0f / 0.07f)

#define OUTS_ELEMS   (6LL * Bv * K1v)              // 1,572,864
#define MEM_ELEMS    ((long long)NMEM * Dv)        // 25,600,000 floats / bank
#define MEM_F4       (MEM_ELEMS / 4)               // 6,400,000 float4 / bank
#define TOTAL_F4     (4 * MEM_F4)                  // 25,600,000 float4 across banks

#define GATHER_BLOCKS 32768                        // B * K1 / 8 warps-per-block
#define COPY_BLOCKS   4096
#define TOTAL_BLOCKS  (GATHER_BLOCKS + COPY_BLOCKS) // 36864; pattern: bid%9==8 -> copy

// ---------------------------------------------------------------------------
// Fused kernel: gather-dots (8 warps = 8 (b,k) tasks per block) interleaved
// with grid-stride float4 copy of the 4 memory banks into the output.
// outs layout [6, B, K1], stack order:
//   0: w_ori.l  1: w_l.ab  2: w_ab.ori  3: w_comp.ab  4: w_comp.l  5: w_ori.comp
// ---------------------------------------------------------------------------
__global__ __launch_bounds__(256) void fused_gather_copy_kernel(
    const float* __restrict__ l,
    const float* __restrict__ ab,
    const float* __restrict__ ori,
    const float* __restrict__ comp,
    const int*   __restrict__ idx,
    const float* __restrict__ mem_l,
    const float* __restrict__ mem_ab,
    const float* __restrict__ mem_ori,
    const float* __restrict__ mem_comp,
    float* __restrict__ outs,
    float* __restrict__ out_banks)   // contiguous: [mem_l|mem_ab|mem_ori|mem_comp]
{
    const int bid = blockIdx.x;
    const int r   = bid % 9;
    const int q   = bid / 9;
    const int tid = threadIdx.x;

    if (r == 8) {
        // -------- copy branch: grid-stride over all 4 banks as float4 --------
        const float4* srcs[4] = {
            reinterpret_cast<const float4*>(mem_l),
            reinterpret_cast<const float4*>(mem_ab),
            reinterpret_cast<const float4*>(mem_ori),
            reinterpret_cast<const float4*>(mem_comp)
        };
        float4* dst = reinterpret_cast<float4*>(out_banks);
        const long long stride = (long long)COPY_BLOCKS * 256;
        for (long long i = (long long)q * 256 + tid; i < TOTAL_F4; i += stride) {
            const int  bank = (int)(i / MEM_F4);
            const long long off = i - (long long)bank * MEM_F4;
            dst[i] = srcs[bank][off];
        }
        return;
    }

    // -------- gather branch --------
    const int g      = q * 8 + r;        // 0 .. 32767
    const int b      = g >> 8;           // g / 256
    const int kchunk = g & 255;          // g % 256

    __shared__ float4 s_l[32], s_ab[32], s_ori[32], s_comp[32];
    __shared__ int    s_idx[8];

    if (tid < 32) {
        s_l [tid] = reinterpret_cast<const float4*>(l  + b * Dv)[tid];
        s_ab[tid] = reinterpret_cast<const float4*>(ab + b * Dv)[tid];
    } else if (tid < 64) {
        const int t = tid - 32;
        s_ori [t] = reinterpret_cast<const float4*>(ori  + b * Dv)[t];
        s_comp[t] = reinterpret_cast<const float4*>(comp + b * Dv)[t];
    } else if (tid < 72) {
        s_idx[tid - 64] = idx[b * K1v + kchunk * 8 + (tid - 64)];
    }
    __syncthreads();

    const int warp = tid >> 5;
    const int lane = tid & 31;
    const int k    = kchunk * 8 + warp;
    const long long row = s_idx[warp];

    const float4 wl  = reinterpret_cast<const float4*>(mem_l    + row * Dv)[lane];
    const float4 wab = reinterpret_cast<const float4*>(mem_ab   + row * Dv)[lane];
    const float4 wor = reinterpret_cast<const float4*>(mem_ori  + row * Dv)[lane];
    const float4 wco = reinterpret_cast<const float4*>(mem_comp + row * Dv)[lane];

    const float4 vl  = s_l[lane];
    const float4 vab = s_ab[lane];
    const float4 vor = s_ori[lane];
    const float4 vco = s_comp[lane];

    float s0 = wor.x * vl.x  + wor.y * vl.y  + wor.z * vl.z  + wor.w * vl.w;
    float s1 = wl.x  * vab.x + wl.y  * vab.y + wl.z  * vab.z + wl.w  * vab.w;
    float s2 = wab.x * vor.x + wab.y * vor.y + wab.z * vor.z + wab.w * vor.w;
    float s3 = wco.x * vab.x + wco.y * vab.y + wco.z * vab.z + wco.w * vab.w;
    float s4 = wco.x * vl.x  + wco.y * vl.y  + wco.z * vl.z  + wco.w * vl.w;
    float s5 = wor.x * vco.x + wor.y * vco.y + wor.z * vco.z + wor.w * vco.w;

    #pragma unroll
    for (int off = 16; off > 0; off >>= 1) {
        s0 += __shfl_xor_sync(0xFFFFFFFFu, s0, off);
        s1 += __shfl_xor_sync(0xFFFFFFFFu, s1, off);
        s2 += __shfl_xor_sync(0xFFFFFFFFu, s2, off);
        s3 += __shfl_xor_sync(0xFFFFFFFFu, s3, off);
        s4 += __shfl_xor_sync(0xFFFFFFFFu, s4, off);
        s5 += __shfl_xor_sync(0xFFFFFFFFu, s5, off);
    }

    if (lane == 0) {
        const long long base   = (long long)b * K1v + k;
        const long long stride = (long long)Bv * K1v;
        outs[0 * stride + base] = s0 * INV_T;
        outs[1 * stride + base] = s1 * INV_T;
        outs[2 * stride + base] = s2 * INV_T;
        outs[3 * stride + base] = s3 * INV_T;
        outs[4 * stride + base] = s4 * INV_T;
        outs[5 * stride + base] = s5 * INV_T;
    }
}

// ---------------------------------------------------------------------------
// Parallel EMA update: one block per b. A block writes only if b is the LAST
// occurrence of its y value ("last index wins" == jnp .at[y].set semantics).
// Reads originals only, so duplicate-y blocks never create read hazards.
// ---------------------------------------------------------------------------
__global__ __launch_bounds__(128) void ema_update_kernel(
    const float* __restrict__ l,
    const float* __restrict__ ab,
    const float* __restrict__ ori,
    const float* __restrict__ comp,
    const int*   __restrict__ y,
    const float* __restrict__ mem_l,
    const float* __restrict__ mem_ab,
    const float* __restrict__ mem_ori,
    const float* __restrict__ mem_comp,
    float* __restrict__ out_banks)
{
    const int b = blockIdx.x;
    const int t = threadIdx.x;  // 0..127

    __shared__ int   s_y[Bv];
    __shared__ int   s_dup;
    __shared__ float red[4][4];

    if (t == 0) s_dup = 0;
    s_y[t] = y[t];
    __syncthreads();

    const int myy = s_y[b];
    if (t > b && s_y[t] == myy) atomicOr(&s_dup, 1);
    __syncthreads();
    if (s_dup) return;   // a later b owns this row

    const float* vs[4] = {l, ab, ori, comp};
    const float* ms[4] = {mem_l, mem_ab, mem_ori, mem_comp};

    const long long row = myy;
    float p[4];
    #pragma unroll
    for (int m = 0; m < 4; ++m) {
        p[m] = ms[m][row * Dv + t] * 0.5f + vs[m][b * Dv + t] * 0.5f;
        float sq = p[m] * p[m];
        #pragma unroll
        for (int off = 16; off > 0; off >>= 1)
            sq += __shfl_xor_sync(0xFFFFFFFFu, sq, off);
        if ((t & 31) == 0) red[m][t >> 5] = sq;
    }
    __syncthreads();

    #pragma unroll
    for (int m = 0; m < 4; ++m) {
        const float inv = rsqrtf(red[m][0] + red[m][1] + red[m][2] + red[m][3]);
        out_banks[(long long)m * MEM_ELEMS + row * Dv + t] = p[m] * inv;
    }
}

// ---------------------------------------------------------------------------
extern "C" void kernel_launch(void* const* d_in, const int* in_sizes, int n_in,
                              void* d_out, int out_size)
{
    const float* l        = (const float*)d_in[0];
    const float* ab       = (const float*)d_in[1];
    const float* ori      = (const float*)d_in[2];
    const float* comp     = (const float*)d_in[3];
    const int*   y        = (const int*)  d_in[4];
    const int*   idx      = (const int*)  d_in[5];
    const float* mem_l    = (const float*)d_in[6];
    const float* mem_ab   = (const float*)d_in[7];
    const float* mem_ori  = (const float*)d_in[8];
    const float* mem_comp = (const float*)d_in[9];

    float* out       = (float*)d_out;
    float* out_outs  = out;
    float* out_banks = out + OUTS_ELEMS;

    fused_gather_copy_kernel<<<TOTAL_BLOCKS, 256>>>(
        l, ab, ori, comp, idx,
        mem_l, mem_ab, mem_ori, mem_comp,
        out_outs, out_banks);

    ema_update_kernel<<<Bv, 128>>>(
        l, ab, ori, comp, y,
        mem_l, mem_ab, mem_ori, mem_comp,
        out_banks);
}

// round 3
// speedup vs baseline: 3.8329x; 1.3719x over previous
#include <cuda_runtime.h>
#include <math.h>

#define Bv    128
#define Dv    128
#define NMEM  200000
#define K1v   2048
#define INV_T (1.0f / 0.07f)

#define OUTS_ELEMS  (6LL * Bv * K1v)
#define MEM_ELEMS   ((long long)NMEM * Dv)
#define NIDX        (Bv * K1v)          // 262144
#define SLOTS       12
#define OVER_CAP    65536

// -------- device scratch (static; no allocations) --------
__device__ int g_count[NMEM];
__device__ int g_owner[NMEM];
__device__ int g_slots[(long long)NMEM * SLOTS];
__device__ int g_over [OVER_CAP];
__device__ int g_nover;

// ---------------------------------------------------------------------------
// Kernel 0: clear scratch (count=0, owner=-1, nover=0)
// ---------------------------------------------------------------------------
__global__ void clear_kernel()
{
    const int stride = gridDim.x * blockDim.x;
    for (int i = blockIdx.x * blockDim.x + threadIdx.x; i < NMEM; i += stride) {
        g_count[i] = 0;
        g_owner[i] = -1;
    }
    if (blockIdx.x == 0 && threadIdx.x == 0) g_nover = 0;
}

// ---------------------------------------------------------------------------
// Kernel 1: build inverse map (row -> flat idx positions) + owner map for EMA
// ---------------------------------------------------------------------------
__global__ void build_kernel(const int* __restrict__ idx,
                             const int* __restrict__ y)
{
    const int tid = blockIdx.x * blockDim.x + threadIdx.x;
    if (tid < NIDX) {
        const int row = idx[tid];
        const int pos = atomicAdd(&g_count[row], 1);
        if (pos < SLOTS) g_slots[(long long)row * SLOTS + pos] = tid;
        else {
            const int o = atomicAdd(&g_nover, 1);
            if (o < OVER_CAP) g_over[o] = tid;
        }
    }
    // owner map: last occurrence of y wins (jnp .at[y].set semantics)
    if (tid < Bv) {
        const int yi = y[tid];
        bool last = true;
        for (int j = tid + 1; j < Bv; ++j)
            if (y[j] == yi) { last = false; break; }
        if (last) g_owner[yi] = tid;
    }
}

// ---------------------------------------------------------------------------
// Kernel 2 (main): single streaming pass over all bank rows.
// One warp per row: load 4 bank rows (float4/lane), write either the copy or
// the fused EMA-updated row to out_banks, then compute the 6 dot products for
// every (b,k) that references this row (inverse map), writing outs.
// Afterwards, warps with gw < n_over handle overflow entries gather-style.
// ---------------------------------------------------------------------------
__global__ __launch_bounds__(256) void main_kernel(
    const float* __restrict__ l,
    const float* __restrict__ ab,
    const float* __restrict__ ori,
    const float* __restrict__ comp,
    const float* __restrict__ mem_l,
    const float* __restrict__ mem_ab,
    const float* __restrict__ mem_ori,
    const float* __restrict__ mem_comp,
    const int*   __restrict__ idx,
    float* __restrict__ outs,
    float* __restrict__ out_banks)
{
    const int warp = threadIdx.x >> 5;
    const int lane = threadIdx.x & 31;
    const long long gw = (long long)blockIdx.x * 8 + warp;   // 0..199999
    const long long r  = gw;

    // ---- load the row across all 4 banks ----
    const float4 wl  = reinterpret_cast<const float4*>(mem_l    + r * Dv)[lane];
    const float4 wab = reinterpret_cast<const float4*>(mem_ab   + r * Dv)[lane];
    const float4 wor = reinterpret_cast<const float4*>(mem_ori  + r * Dv)[lane];
    const float4 wco = reinterpret_cast<const float4*>(mem_comp + r * Dv)[lane];

    const int owner = g_owner[r];
    const int cnt   = g_count[r];

    // ---- write output banks: plain copy, or EMA-updated row ----
    if (owner < 0) {
        reinterpret_cast<float4*>(out_banks + 0 * MEM_ELEMS + r * Dv)[lane] = wl;
        reinterpret_cast<float4*>(out_banks + 1 * MEM_ELEMS + r * Dv)[lane] = wab;
        reinterpret_cast<float4*>(out_banks + 2 * MEM_ELEMS + r * Dv)[lane] = wor;
        reinterpret_cast<float4*>(out_banks + 3 * MEM_ELEMS + r * Dv)[lane] = wco;
    } else {
        const float* vsrc[4] = {l, ab, ori, comp};
        const float4 wsrc[4] = {wl, wab, wor, wco};
        #pragma unroll
        for (int m = 0; m < 4; ++m) {
            const float4 v = reinterpret_cast<const float4*>(vsrc[m] + owner * Dv)[lane];
            float4 p;
            p.x = wsrc[m].x * 0.5f + v.x * 0.5f;
            p.y = wsrc[m].y * 0.5f + v.y * 0.5f;
            p.z = wsrc[m].z * 0.5f + v.z * 0.5f;
            p.w = wsrc[m].w * 0.5f + v.w * 0.5f;
            float sq = p.x * p.x + p.y * p.y + p.z * p.z + p.w * p.w;
            #pragma unroll
            for (int off = 16; off > 0; off >>= 1)
                sq += __shfl_xor_sync(0xFFFFFFFFu, sq, off);
            const float inv = rsqrtf(sq);
            p.x *= inv; p.y *= inv; p.z *= inv; p.w *= inv;
            reinterpret_cast<float4*>(out_banks + (long long)m * MEM_ELEMS + r * Dv)[lane] = p;
        }
    }

    // ---- dot products for every (b,k) referencing this row ----
    const int nent = cnt < SLOTS ? cnt : SLOTS;
    for (int e = 0; e < nent; ++e) {
        const int ent = g_slots[r * SLOTS + e];
        const int b   = ent >> 11;          // ent / K1v
        const int k   = ent & (K1v - 1);

        const float4 vl  = __ldg(reinterpret_cast<const float4*>(l    + b * Dv) + lane);
        const float4 vab = __ldg(reinterpret_cast<const float4*>(ab   + b * Dv) + lane);
        const float4 vor = __ldg(reinterpret_cast<const float4*>(ori  + b * Dv) + lane);
        const float4 vco = __ldg(reinterpret_cast<const float4*>(comp + b * Dv) + lane);

        float s0 = wor.x*vl.x  + wor.y*vl.y  + wor.z*vl.z  + wor.w*vl.w;
        float s1 = wl.x *vab.x + wl.y *vab.y + wl.z *vab.z + wl.w *vab.w;
        float s2 = wab.x*vor.x + wab.y*vor.y + wab.z*vor.z + wab.w*vor.w;
        float s3 = wco.x*vab.x + wco.y*vab.y + wco.z*vab.z + wco.w*vab.w;
        float s4 = wco.x*vl.x  + wco.y*vl.y  + wco.z*vl.z  + wco.w*vl.w;
        float s5 = wor.x*vco.x + wor.y*vco.y + wor.z*vco.z + wor.w*vco.w;

        #pragma unroll
        for (int off = 16; off > 0; off >>= 1) {
            s0 += __shfl_xor_sync(0xFFFFFFFFu, s0, off);
            s1 += __shfl_xor_sync(0xFFFFFFFFu, s1, off);
            s2 += __shfl_xor_sync(0xFFFFFFFFu, s2, off);
            s3 += __shfl_xor_sync(0xFFFFFFFFu, s3, off);
            s4 += __shfl_xor_sync(0xFFFFFFFFu, s4, off);
            s5 += __shfl_xor_sync(0xFFFFFFFFu, s5, off);
        }
        if (lane == 0) {
            const long long base   = (long long)b * K1v + k;
            const long long stride = (long long)Bv * K1v;
            outs[0 * stride + base] = s0 * INV_T;
            outs[1 * stride + base] = s1 * INV_T;
            outs[2 * stride + base] = s2 * INV_T;
            outs[3 * stride + base] = s3 * INV_T;
            outs[4 * stride + base] = s4 * INV_T;
            outs[5 * stride + base] = s5 * INV_T;
        }
    }

    // ---- overflow entries (vanishingly rare): gather-style ----
    const int nover = g_nover;
    if (gw < nover) {
        const int ent = g_over[gw];
        const int b   = ent >> 11;
        const int k   = ent & (K1v - 1);
        const long long row = idx[ent];

        const float4 ol  = reinterpret_cast<const float4*>(mem_l    + row * Dv)[lane];
        const float4 oab = reinterpret_cast<const float4*>(mem_ab   + row * Dv)[lane];
        const float4 oor = reinterpret_cast<const float4*>(mem_ori  + row * Dv)[lane];
        const float4 oco = reinterpret_cast<const float4*>(mem_comp + row * Dv)[lane];

        const float4 vl  = __ldg(reinterpret_cast<const float4*>(l    + b * Dv) + lane);
        const float4 vab = __ldg(reinterpret_cast<const float4*>(ab   + b * Dv) + lane);
        const float4 vor = __ldg(reinterpret_cast<const float4*>(ori  + b * Dv) + lane);
        const float4 vco = __ldg(reinterpret_cast<const float4*>(comp + b * Dv) + lane);

        float s0 = oor.x*vl.x  + oor.y*vl.y  + oor.z*vl.z  + oor.w*vl.w;
        float s1 = ol.x *vab.x + ol.y *vab.y + ol.z *vab.z + ol.w *vab.w;
        float s2 = oab.x*vor.x + oab.y*vor.y + oab.z*vor.z + oab.w*vor.w;
        float s3 = oco.x*vab.x + oco.y*vab.y + oco.z*vab.z + oco.w*vab.w;
        float s4 = oco.x*vl.x  + oco.y*vl.y  + oco.z*vl.z  + oco.w*vl.w;
        float s5 = oor.x*vco.x + oor.y*vco.y + oor.z*vco.z + oor.w*vco.w;

        #pragma unroll
        for (int off = 16; off > 0; off >>= 1) {
            s0 += __shfl_xor_sync(0xFFFFFFFFu, s0, off);
            s1 += __shfl_xor_sync(0xFFFFFFFFu, s1, off);
            s2 += __shfl_xor_sync(0xFFFFFFFFu, s2, off);
            s3 += __shfl_xor_sync(0xFFFFFFFFu, s3, off);
            s4 += __shfl_xor_sync(0xFFFFFFFFu, s4, off);
            s5 += __shfl_xor_sync(0xFFFFFFFFu, s5, off);
        }
        if (lane == 0) {
            const long long base   = (long long)b * K1v + k;
            const long long stride = (long long)Bv * K1v;
            outs[0 * stride + base] = s0 * INV_T;
            outs[1 * stride + base] = s1 * INV_T;
            outs[2 * stride + base] = s2 * INV_T;
            outs[3 * stride + base] = s3 * INV_T;
            outs[4 * stride + base] = s4 * INV_T;
            outs[5 * stride + base] = s5 * INV_T;
        }
    }
}

// ---------------------------------------------------------------------------
extern "C" void kernel_launch(void* const* d_in, const int* in_sizes, int n_in,
                              void* d_out, int out_size)
{
    const float* l        = (const float*)d_in[0];
    const float* ab       = (const float*)d_in[1];
    const float* ori      = (const float*)d_in[2];
    const float* comp     = (const float*)d_in[3];
    const int*   y        = (const int*)  d_in[4];
    const int*   idx      = (const int*)  d_in[5];
    const float* mem_l    = (const float*)d_in[6];
    const float* mem_ab   = (const float*)d_in[7];
    const float* mem_ori  = (const float*)d_in[8];
    const float* mem_comp = (const float*)d_in[9];

    float* out       = (float*)d_out;
    float* out_outs  = out;
    float* out_banks = out + OUTS_ELEMS;

    clear_kernel<<<296, 256>>>();
    build_kernel<<<(NIDX + 255) / 256, 256>>>(idx, y);
    main_kernel<<<NMEM / 8, 256>>>(l, ab, ori, comp,
                                   mem_l, mem_ab, mem_ori, mem_comp,
                                   idx, out_outs, out_banks);
}